// round 5
// baseline (speedup 1.0000x reference)
#include <cuda_runtime.h>

#define TPB 256

namespace {
constexpr int NODE = 112;
constexpr int XP   = 116;   // x tile pitch (floats)
constexpr int HP   = 260;   // H buffer pitch (up to 256 cols)
constexpr int TP1  = 36;    // stage-1 h1-block temp pitch (32 cols)
constexpr int TP2  = 68;    // stage-2 temp / g4 pitch (64 cols)
constexpr int GP3  = 132;   // g3 pitch (128 cols)
constexpr int SMEM_FLOATS = NODE*XP + NODE*HP + NODE*GP3 + 256;
constexpr int SMEM_BYTES  = SMEM_FLOATS * 4;   // 228,608 B  (<= 232,448 max)
}

__device__ __forceinline__ float frelu(float v) { return v > 0.f ? v : 0.f; }

__global__ __launch_bounds__(TPB, 1) void gcn_fused(
    const float* __restrict__ x,
    const float* __restrict__ W1, const float* __restrict__ b1,
    const float* __restrict__ W2, const float* __restrict__ b2,
    const float* __restrict__ W3, const float* __restrict__ b3,
    const float* __restrict__ W4, const float* __restrict__ b4,
    const float* __restrict__ W5, const float* __restrict__ b5,
    const float* __restrict__ Wf, const float* __restrict__ bf,
    float* __restrict__ out)
{
    extern __shared__ float sm[];
    float* xs = sm;                       // [112][116]
    float* Hb = sm + NODE*XP;             // [112][260]
    float* Gb = Hb + NODE*HP;             // [112][132] (reused with pitches 36/68/132)
    float* g5 = Gb + NODE*GP3;            // [112]
    float* red = g5 + NODE;               // [112]

    const int tid = threadIdx.x;
    const int bidx = blockIdx.x;
    const int tr = tid & 15;              // 16 thread-rows
    const int tc = tid >> 4;              // 16 thread-cols
    const int m0 = tr * 7;                // each thread-row owns 7 matrix rows

    // ---------------- stage 0: load x tile, zero g2 accumulator ----------------
    {
        const float4* xg = reinterpret_cast<const float4*>(x + (size_t)bidx * NODE * NODE);
        #pragma unroll 4
        for (int i = tid; i < NODE * 28; i += TPB) {
            int r = i / 28, c = i - r * 28;
            *reinterpret_cast<float4*>(&xs[r*XP + c*4]) = xg[i];
        }
        float4 z = make_float4(0.f, 0.f, 0.f, 0.f);
        #pragma unroll 4
        for (int i = tid; i < NODE * 64; i += TPB) {
            int r = i >> 6, c = i & 63;
            *reinterpret_cast<float4*>(&Hb[r*HP + c*4]) = z;
        }
    }
    __syncthreads();

    // ---------------- stage 1: fused layer1 -> g2 = h1 @ W2^T (into Hb) --------
    // h1 = relu(x @ W1^T + b1), never materialized in full; 32-col blocks.
    #pragma unroll 1
    for (int cb = 0; cb < 8; cb++) {
        const int c0 = cb * 32;
        // (a) T[112,32] = relu(x @ W1[c0:c0+32]^T + b1[c0:c0+32])   (T in Gb, pitch 36)
        {
            const int d = c0 + tc * 2;
            const float* wA = W1 + (size_t)d * NODE;
            const float* wB = wA + NODE;
            float acc0[7], acc1[7];
            #pragma unroll
            for (int i = 0; i < 7; i++) { acc0[i] = 0.f; acc1[i] = 0.f; }
            #pragma unroll 1
            for (int k = 0; k < NODE; k += 4) {
                float4 a4 = *reinterpret_cast<const float4*>(wA + k);
                float4 c4 = *reinterpret_cast<const float4*>(wB + k);
                #pragma unroll
                for (int i = 0; i < 7; i++) {
                    float4 xv = *reinterpret_cast<const float4*>(&xs[(m0+i)*XP + k]);
                    acc0[i] = fmaf(xv.x, a4.x, acc0[i]);
                    acc0[i] = fmaf(xv.y, a4.y, acc0[i]);
                    acc0[i] = fmaf(xv.z, a4.z, acc0[i]);
                    acc0[i] = fmaf(xv.w, a4.w, acc0[i]);
                    acc1[i] = fmaf(xv.x, c4.x, acc1[i]);
                    acc1[i] = fmaf(xv.y, c4.y, acc1[i]);
                    acc1[i] = fmaf(xv.z, c4.z, acc1[i]);
                    acc1[i] = fmaf(xv.w, c4.w, acc1[i]);
                }
            }
            float bb0 = b1[d], bb1 = b1[d+1];
            #pragma unroll
            for (int i = 0; i < 7; i++) {
                Gb[(m0+i)*TP1 + tc*2    ] = frelu(acc0[i] + bb0);
                Gb[(m0+i)*TP1 + tc*2 + 1] = frelu(acc1[i] + bb1);
            }
        }
        __syncthreads();
        // (b) g2[:, :] += T @ W2[:, c0:c0+32]^T  (RMW into Hb), N split in 2 halves of 128
        #pragma unroll 1
        for (int half = 0; half < 2; half++) {
            const int d0 = half * 128 + tc * 8;
            float acc[7][8];
            #pragma unroll
            for (int i = 0; i < 7; i++) {
                float4 p = *reinterpret_cast<const float4*>(&Hb[(m0+i)*HP + d0]);
                float4 q = *reinterpret_cast<const float4*>(&Hb[(m0+i)*HP + d0 + 4]);
                acc[i][0]=p.x; acc[i][1]=p.y; acc[i][2]=p.z; acc[i][3]=p.w;
                acc[i][4]=q.x; acc[i][5]=q.y; acc[i][6]=q.z; acc[i][7]=q.w;
            }
            #pragma unroll 1
            for (int kk = 0; kk < 32; kk += 4) {
                float4 wv[8];
                #pragma unroll
                for (int j = 0; j < 8; j++)
                    wv[j] = *reinterpret_cast<const float4*>(W2 + (size_t)(d0+j)*256 + c0 + kk);
                #pragma unroll
                for (int i = 0; i < 7; i++) {
                    float4 tv = *reinterpret_cast<const float4*>(&Gb[(m0+i)*TP1 + kk]);
                    #pragma unroll
                    for (int j = 0; j < 8; j++) {
                        acc[i][j] = fmaf(tv.x, wv[j].x, acc[i][j]);
                        acc[i][j] = fmaf(tv.y, wv[j].y, acc[i][j]);
                        acc[i][j] = fmaf(tv.z, wv[j].z, acc[i][j]);
                        acc[i][j] = fmaf(tv.w, wv[j].w, acc[i][j]);
                    }
                }
            }
            #pragma unroll
            for (int i = 0; i < 7; i++) {
                float4 p = make_float4(acc[i][0],acc[i][1],acc[i][2],acc[i][3]);
                float4 q = make_float4(acc[i][4],acc[i][5],acc[i][6],acc[i][7]);
                *reinterpret_cast<float4*>(&Hb[(m0+i)*HP + d0    ]) = p;
                *reinterpret_cast<float4*>(&Hb[(m0+i)*HP + d0 + 4]) = q;
            }
        }
        __syncthreads();
    }

    // ---------------- stage 2: h2 = relu(x @ g2 + b2), in-place on Hb ----------
    #pragma unroll 1
    for (int db = 0; db < 4; db++) {
        const int dbase = db * 64;
        const int dd = dbase + tc * 4;
        float acc[7][4];
        #pragma unroll
        for (int i = 0; i < 7; i++)
            #pragma unroll
            for (int j = 0; j < 4; j++) acc[i][j] = 0.f;
        #pragma unroll 1
        for (int k = 0; k < NODE; k += 4) {
            float4 g0 = *reinterpret_cast<const float4*>(&Hb[(k+0)*HP + dd]);
            float4 g1 = *reinterpret_cast<const float4*>(&Hb[(k+1)*HP + dd]);
            float4 g2 = *reinterpret_cast<const float4*>(&Hb[(k+2)*HP + dd]);
            float4 g3 = *reinterpret_cast<const float4*>(&Hb[(k+3)*HP + dd]);
            #pragma unroll
            for (int i = 0; i < 7; i++) {
                float4 xv = *reinterpret_cast<const float4*>(&xs[(m0+i)*XP + k]);
                acc[i][0] = fmaf(xv.x,g0.x, fmaf(xv.y,g1.x, fmaf(xv.z,g2.x, fmaf(xv.w,g3.x, acc[i][0]))));
                acc[i][1] = fmaf(xv.x,g0.y, fmaf(xv.y,g1.y, fmaf(xv.z,g2.y, fmaf(xv.w,g3.y, acc[i][1]))));
                acc[i][2] = fmaf(xv.x,g0.z, fmaf(xv.y,g1.z, fmaf(xv.z,g2.z, fmaf(xv.w,g3.z, acc[i][2]))));
                acc[i][3] = fmaf(xv.x,g0.w, fmaf(xv.y,g1.w, fmaf(xv.z,g2.w, fmaf(xv.w,g3.w, acc[i][3]))));
            }
        }
        float bb[4];
        #pragma unroll
        for (int j = 0; j < 4; j++) bb[j] = b2[dd + j];
        #pragma unroll
        for (int i = 0; i < 7; i++)
            #pragma unroll
            for (int j = 0; j < 4; j++)
                Gb[(m0+i)*TP2 + tc*4 + j] = frelu(acc[i][j] + bb[j]);
        __syncthreads();
        #pragma unroll 2
        for (int i = tid; i < NODE * 16; i += TPB) {
            int r = i >> 4, c = i & 15;
            *reinterpret_cast<float4*>(&Hb[r*HP + dbase + c*4]) =
                *reinterpret_cast<const float4*>(&Gb[r*TP2 + c*4]);
        }
        __syncthreads();
    }

    // ---------------- stage 3: g3 = h2 @ W3^T  [112,128] -> Gb ------------------
    {
        const int d0 = tc * 8;
        float acc[7][8];
        #pragma unroll
        for (int i = 0; i < 7; i++)
            #pragma unroll
            for (int j = 0; j < 8; j++) acc[i][j] = 0.f;
        #pragma unroll 1
        for (int kk = 0; kk < 256; kk += 4) {
            float4 wv[8];
            #pragma unroll
            for (int j = 0; j < 8; j++)
                wv[j] = *reinterpret_cast<const float4*>(W3 + (size_t)(d0+j)*256 + kk);
            #pragma unroll
            for (int i = 0; i < 7; i++) {
                float4 hv = *reinterpret_cast<const float4*>(&Hb[(m0+i)*HP + kk]);
                #pragma unroll
                for (int j = 0; j < 8; j++) {
                    acc[i][j] = fmaf(hv.x, wv[j].x, acc[i][j]);
                    acc[i][j] = fmaf(hv.y, wv[j].y, acc[i][j]);
                    acc[i][j] = fmaf(hv.z, wv[j].z, acc[i][j]);
                    acc[i][j] = fmaf(hv.w, wv[j].w, acc[i][j]);
                }
            }
        }
        __syncthreads();   // all h2 reads done before Gb overwritten
        #pragma unroll
        for (int i = 0; i < 7; i++)
            #pragma unroll
            for (int j = 0; j < 8; j++)
                Gb[(m0+i)*GP3 + d0 + j] = acc[i][j];
    }
    __syncthreads();

    // ---------------- stage 4: h3 = relu(x @ g3 + b3) [112,128] -> Hb -----------
    {
        const int dd = tc * 8;
        float acc[7][8];
        #pragma unroll
        for (int i = 0; i < 7; i++)
            #pragma unroll
            for (int j = 0; j < 8; j++) acc[i][j] = 0.f;
        #pragma unroll 1
        for (int k = 0; k < NODE; k += 4) {
            float4 ga[4], gb[4];
            #pragma unroll
            for (int kk = 0; kk < 4; kk++) {
                ga[kk] = *reinterpret_cast<const float4*>(&Gb[(k+kk)*GP3 + dd]);
                gb[kk] = *reinterpret_cast<const float4*>(&Gb[(k+kk)*GP3 + dd + 4]);
            }
            #pragma unroll
            for (int i = 0; i < 7; i++) {
                float4 xv = *reinterpret_cast<const float4*>(&xs[(m0+i)*XP + k]);
                acc[i][0] = fmaf(xv.x,ga[0].x, fmaf(xv.y,ga[1].x, fmaf(xv.z,ga[2].x, fmaf(xv.w,ga[3].x, acc[i][0]))));
                acc[i][1] = fmaf(xv.x,ga[0].y, fmaf(xv.y,ga[1].y, fmaf(xv.z,ga[2].y, fmaf(xv.w,ga[3].y, acc[i][1]))));
                acc[i][2] = fmaf(xv.x,ga[0].z, fmaf(xv.y,ga[1].z, fmaf(xv.z,ga[2].z, fmaf(xv.w,ga[3].z, acc[i][2]))));
                acc[i][3] = fmaf(xv.x,ga[0].w, fmaf(xv.y,ga[1].w, fmaf(xv.z,ga[2].w, fmaf(xv.w,ga[3].w, acc[i][3]))));
                acc[i][4] = fmaf(xv.x,gb[0].x, fmaf(xv.y,gb[1].x, fmaf(xv.z,gb[2].x, fmaf(xv.w,gb[3].x, acc[i][4]))));
                acc[i][5] = fmaf(xv.x,gb[0].y, fmaf(xv.y,gb[1].y, fmaf(xv.z,gb[2].y, fmaf(xv.w,gb[3].y, acc[i][5]))));
                acc[i][6] = fmaf(xv.x,gb[0].z, fmaf(xv.y,gb[1].z, fmaf(xv.z,gb[2].z, fmaf(xv.w,gb[3].z, acc[i][6]))));
                acc[i][7] = fmaf(xv.x,gb[0].w, fmaf(xv.y,gb[1].w, fmaf(xv.z,gb[2].w, fmaf(xv.w,gb[3].w, acc[i][7]))));
            }
        }
        float bb[8];
        #pragma unroll
        for (int j = 0; j < 8; j++) bb[j] = b3[dd + j];
        #pragma unroll
        for (int i = 0; i < 7; i++)
            #pragma unroll
            for (int j = 0; j < 8; j++)
                Hb[(m0+i)*HP + dd + j] = frelu(acc[i][j] + bb[j]);
    }
    __syncthreads();

    // ---------------- stage 5: g4 = h3 @ W4^T [112,64] -> Gb (pitch 68) ---------
    {
        const int d0 = tc * 4;
        float acc[7][4];
        #pragma unroll
        for (int i = 0; i < 7; i++)
            #pragma unroll
            for (int j = 0; j < 4; j++) acc[i][j] = 0.f;
        #pragma unroll 1
        for (int kk = 0; kk < 128; kk += 4) {
            float4 wv[4];
            #pragma unroll
            for (int j = 0; j < 4; j++)
                wv[j] = *reinterpret_cast<const float4*>(W4 + (size_t)(d0+j)*128 + kk);
            #pragma unroll
            for (int i = 0; i < 7; i++) {
                float4 hv = *reinterpret_cast<const float4*>(&Hb[(m0+i)*HP + kk]);
                #pragma unroll
                for (int j = 0; j < 4; j++) {
                    acc[i][j] = fmaf(hv.x, wv[j].x, acc[i][j]);
                    acc[i][j] = fmaf(hv.y, wv[j].y, acc[i][j]);
                    acc[i][j] = fmaf(hv.z, wv[j].z, acc[i][j]);
                    acc[i][j] = fmaf(hv.w, wv[j].w, acc[i][j]);
                }
            }
        }
        __syncthreads();   // g3 reads (none here) / prior Gb usage done
        #pragma unroll
        for (int i = 0; i < 7; i++)
            #pragma unroll
            for (int j = 0; j < 4; j++)
                Gb[(m0+i)*TP2 + d0 + j] = acc[i][j];
    }
    __syncthreads();

    // ---------------- stage 6: h4 = relu(x @ g4 + b4) [112,64] -> Hb ------------
    {
        const int dd = tc * 4;
        float acc[7][4];
        #pragma unroll
        for (int i = 0; i < 7; i++)
            #pragma unroll
            for (int j = 0; j < 4; j++) acc[i][j] = 0.f;
        #pragma unroll 1
        for (int k = 0; k < NODE; k += 4) {
            float4 g0 = *reinterpret_cast<const float4*>(&Gb[(k+0)*TP2 + dd]);
            float4 g1 = *reinterpret_cast<const float4*>(&Gb[(k+1)*TP2 + dd]);
            float4 g2 = *reinterpret_cast<const float4*>(&Gb[(k+2)*TP2 + dd]);
            float4 g3 = *reinterpret_cast<const float4*>(&Gb[(k+3)*TP2 + dd]);
            #pragma unroll
            for (int i = 0; i < 7; i++) {
                float4 xv = *reinterpret_cast<const float4*>(&xs[(m0+i)*XP + k]);
                acc[i][0] = fmaf(xv.x,g0.x, fmaf(xv.y,g1.x, fmaf(xv.z,g2.x, fmaf(xv.w,g3.x, acc[i][0]))));
                acc[i][1] = fmaf(xv.x,g0.y, fmaf(xv.y,g1.y, fmaf(xv.z,g2.y, fmaf(xv.w,g3.y, acc[i][1]))));
                acc[i][2] = fmaf(xv.x,g0.z, fmaf(xv.y,g1.z, fmaf(xv.z,g2.z, fmaf(xv.w,g3.z, acc[i][2]))));
                acc[i][3] = fmaf(xv.x,g0.w, fmaf(xv.y,g1.w, fmaf(xv.z,g2.w, fmaf(xv.w,g3.w, acc[i][3]))));
            }
        }
        float bb[4];
        #pragma unroll
        for (int j = 0; j < 4; j++) bb[j] = b4[dd + j];
        #pragma unroll
        for (int i = 0; i < 7; i++)
            #pragma unroll
            for (int j = 0; j < 4; j++)
                Hb[(m0+i)*HP + dd + j] = frelu(acc[i][j] + bb[j]);
    }
    __syncthreads();

    // ---------------- stage 7: g5 = h4 @ W5^T  [112] ---------------------------
    if (tid < NODE) {
        float s = 0.f;
        #pragma unroll
        for (int c = 0; c < 64; c += 4) {
            float4 hv = *reinterpret_cast<const float4*>(&Hb[tid*HP + c]);
            float4 wv = *reinterpret_cast<const float4*>(W5 + c);
            s = fmaf(hv.x, wv.x, s);
            s = fmaf(hv.y, wv.y, s);
            s = fmaf(hv.z, wv.z, s);
            s = fmaf(hv.w, wv.w, s);
        }
        g5[tid] = s;
    }
    __syncthreads();

    // ---------------- stage 8: h5 = relu(x @ g5 + b5); partial products ---------
    if (tid < NODE) {
        float s = b5[0];
        #pragma unroll 4
        for (int m = 0; m < NODE; m++)
            s = fmaf(xs[tid*XP + m], g5[m], s);
        red[tid] = frelu(s) * Wf[tid];
    }
    __syncthreads();

    // ---------------- stage 9: out[b] = sum(red) + bf ---------------------------
    if (tid == 0) {
        float s = bf[0];
        #pragma unroll 4
        for (int n = 0; n < NODE; n++) s += red[n];
        out[bidx] = s;
    }
}

extern "C" void kernel_launch(void* const* d_in, const int* in_sizes, int n_in,
                              void* d_out, int out_size)
{
    const float* x  = (const float*)d_in[0];
    const float* W1 = (const float*)d_in[1];
    const float* b1 = (const float*)d_in[2];
    const float* W2 = (const float*)d_in[3];
    const float* b2 = (const float*)d_in[4];
    const float* W3 = (const float*)d_in[5];
    const float* b3 = (const float*)d_in[6];
    const float* W4 = (const float*)d_in[7];
    const float* b4 = (const float*)d_in[8];
    const float* W5 = (const float*)d_in[9];
    const float* b5 = (const float*)d_in[10];
    const float* Wf = (const float*)d_in[11];
    const float* bf = (const float*)d_in[12];
    float* out = (float*)d_out;

    const int batch = in_sizes[0] / (NODE * NODE);   // 4096

    cudaFuncSetAttribute(gcn_fused, cudaFuncAttributeMaxDynamicSharedMemorySize, SMEM_BYTES);
    gcn_fused<<<batch, TPB, SMEM_BYTES>>>(x, W1, b1, W2, b2, W3, b3, W4, b4,
                                          W5, b5, Wf, bf, out);
}